// round 14
// baseline (speedup 1.0000x reference)
#include <cuda_runtime.h>
#include <math.h>

#define T_NUMC   1024
#define DET_NUMC 1024
#define EE       65536       // T_NUM * DEG
#define TWO_E    131072
#define NNODES   2048
#define D_EMBC   256
#define LAMC     5.0f
#define EPSC     1e-9f
#define SBLK     32          // persistent sinkhorn blocks (1024 thr each)

// ---------------- scratch (device globals; no allocation allowed) ----------------
__device__ float g_node[NNODES * D_EMBC];          // row-major (GEMM A operand)
__device__ float g_PT[64 * NNODES];                // P transposed: PT[h][n]
__device__ float g_QT[64 * NNODES];                // Q transposed: QT[h][n]
__device__ float g_emb[TWO_E];
__device__ float g_msg[NNODES * D_EMBC];           // row-major (GEMM A operand)
__device__ float g_OT[D_EMBC * NNODES];            // out transposed: OT[f][n]
__device__ float g_norm[NNODES];
__device__ int   g_cnt[NNODES];
__device__ int   g_csc_eid[NNODES * 64];
__device__ int   g_csc_src[NNODES * 64];
__device__ float g_mval[EE];    // M0 nnz, row-major by tracklet (edge e -> row e/64)
__device__ int   g_dstd[EE];    // det column of edge e
__device__ float g_cval[EE];    // M0 nnz, column-major by det
__device__ int   g_csrc[EE];    // tracklet row of column-ordered nnz
__device__ int   g_inv[EE];     // forward edge e -> its column-view slot
__device__ float g_u[1025];
__device__ float g_v[1025];
__device__ volatile int g_bar;

__device__ __forceinline__ float warpsum(float x) {
    #pragma unroll
    for (int o = 16; o > 0; o >>= 1) x += __shfl_xor_sync(0xffffffffu, x, o);
    return x;
}

// ---------------- CSC build; fills column view + inv index; inits u,v ------------
__global__ void csc_build(const int* __restrict__ ei) {
    int e = blockIdx.x * blockDim.x + threadIdx.x;
    if (e < 1025) { g_u[e] = 1.f; g_v[e] = 1.f; }
    if (e >= TWO_E) return;
    int s = ei[e];
    int d = ei[TWO_E + e];
    int slot = atomicAdd(&g_cnt[d], 1);
    if (slot < 64) {
        g_csc_eid[d * 64 + slot] = e;
        g_csc_src[d * 64 + slot] = s;
        if (d >= T_NUMC) {                      // forward edge: column view entry
            int ci = (d - T_NUMC) * 64 + slot;
            g_csrc[ci] = s;
            g_inv[e] = ci;
        }
    }
}

// ---------------- double-buffered tiled fp32 GEMM --------------------------------
// C = [relu]( A@B (+ A2@B2) (+ bias) ).  BM=BN=64, BK=16, 256 thr, 4x4/thread.
// TRANSC: write C transposed as C[col*M + row] (feature-major).
template <bool RELU, bool DUAL, bool TRANSC>
__global__ void sgemm(const float* __restrict__ A, const float* __restrict__ B,
                      const float* __restrict__ A2, const float* __restrict__ B2,
                      const float* __restrict__ bias, float* __restrict__ C,
                      int M, int N, int K) {
    __shared__ float As[2][64][16];
    __shared__ float Bs[2][16][64];
    __shared__ float As2[DUAL ? 2 : 1][DUAL ? 64 : 1][16];
    __shared__ float Bs2[DUAL ? 2 : 1][DUAL ? 16 : 1][64];

    int tid = threadIdx.x;
    int rowB = blockIdx.y * 64, colB = blockIdx.x * 64;
    int tx = tid & 15, ty = tid >> 4;
    int ar = tid >> 2, ac = (tid & 3) << 2;
    int br = tid >> 4, bc = (tid & 15) << 2;

    float acc[4][4] = {};
    int nT = K / 16;

    float4 ra = *(const float4*)&A[(size_t)(rowB + ar) * K + ac];
    float4 rb = *(const float4*)&B[(size_t)br * N + colB + bc];
    float4 ra2, rb2;
    if (DUAL) {
        ra2 = *(const float4*)&A2[(size_t)(rowB + ar) * K + ac];
        rb2 = *(const float4*)&B2[(size_t)br * N + colB + bc];
    }
    *(float4*)&As[0][ar][ac] = ra;
    *(float4*)&Bs[0][br][bc] = rb;
    if (DUAL) {
        *(float4*)&As2[0][ar][ac] = ra2;
        *(float4*)&Bs2[0][br][bc] = rb2;
    }
    __syncthreads();

    for (int t = 0; t < nT; t++) {
        int cur = t & 1;
        if (t + 1 < nT) {
            int k0 = (t + 1) * 16;
            ra = *(const float4*)&A[(size_t)(rowB + ar) * K + k0 + ac];
            rb = *(const float4*)&B[(size_t)(k0 + br) * N + colB + bc];
            if (DUAL) {
                ra2 = *(const float4*)&A2[(size_t)(rowB + ar) * K + k0 + ac];
                rb2 = *(const float4*)&B2[(size_t)(k0 + br) * N + colB + bc];
            }
        }
        #pragma unroll
        for (int kk = 0; kk < 16; kk++) {
            float a[4];
            #pragma unroll
            for (int i = 0; i < 4; i++) a[i] = As[cur][ty * 4 + i][kk];
            float4 bv = *(float4*)&Bs[cur][kk][tx * 4];
            #pragma unroll
            for (int i = 0; i < 4; i++) {
                acc[i][0] += a[i] * bv.x;
                acc[i][1] += a[i] * bv.y;
                acc[i][2] += a[i] * bv.z;
                acc[i][3] += a[i] * bv.w;
            }
            if (DUAL) {
                float a2[4];
                #pragma unroll
                for (int i = 0; i < 4; i++) a2[i] = As2[cur][ty * 4 + i][kk];
                float4 bv2 = *(float4*)&Bs2[cur][kk][tx * 4];
                #pragma unroll
                for (int i = 0; i < 4; i++) {
                    acc[i][0] += a2[i] * bv2.x;
                    acc[i][1] += a2[i] * bv2.y;
                    acc[i][2] += a2[i] * bv2.z;
                    acc[i][3] += a2[i] * bv2.w;
                }
            }
        }
        if (t + 1 < nT) {
            int nxt = cur ^ 1;
            *(float4*)&As[nxt][ar][ac] = ra;
            *(float4*)&Bs[nxt][br][bc] = rb;
            if (DUAL) {
                *(float4*)&As2[nxt][ar][ac] = ra2;
                *(float4*)&Bs2[nxt][br][bc] = rb2;
            }
        }
        __syncthreads();
    }
    if (TRANSC) {
        #pragma unroll
        for (int j = 0; j < 4; j++) {
            int col = colB + tx * 4 + j;
            float b = bias ? bias[col] : 0.f;
            float4 w;
            w.x = acc[0][j] + b; w.y = acc[1][j] + b;
            w.z = acc[2][j] + b; w.w = acc[3][j] + b;
            if (RELU) {
                w.x = fmaxf(w.x, 0.f); w.y = fmaxf(w.y, 0.f);
                w.z = fmaxf(w.z, 0.f); w.w = fmaxf(w.w, 0.f);
            }
            *(float4*)&C[(size_t)col * M + rowB + ty * 4] = w;
        }
    } else {
        #pragma unroll
        for (int i = 0; i < 4; i++) {
            int row = rowB + ty * 4 + i;
            #pragma unroll
            for (int j = 0; j < 4; j++) {
                int col = colB + tx * 4 + j;
                float v = acc[i][j];
                if (bias) v += bias[col];
                if (RELU) v = fmaxf(v, 0.f);
                C[(size_t)row * N + col] = v;
            }
        }
    }
}

// ---------------- fused, double-buffered P/Q GEMM -> TRANSPOSED outputs ----------
__global__ void pq_gemm(const float* __restrict__ A, const float* __restrict__ W1a,
                        const float* __restrict__ b1a) {
    __shared__ float As[2][64][16];
    __shared__ float Bs[2][16][64];

    int tid = threadIdx.x;
    int rowB = blockIdx.y * 64;
    bool isQ = (blockIdx.x == 1);
    const float* B = W1a + (isQ ? 256 * 64 : 0);
    float* C = isQ ? g_QT : g_PT;

    int tx = tid & 15, ty = tid >> 4;
    int ar = tid >> 2, ac = (tid & 3) << 2;
    int br = tid >> 4, bc = (tid & 15) << 2;

    float acc[4][4] = {};

    float4 ra = *(const float4*)&A[(size_t)(rowB + ar) * 256 + ac];
    float4 rb = *(const float4*)&B[(size_t)br * 64 + bc];
    *(float4*)&As[0][ar][ac] = ra;
    *(float4*)&Bs[0][br][bc] = rb;
    __syncthreads();

    for (int t = 0; t < 16; t++) {
        int cur = t & 1;
        if (t + 1 < 16) {
            int k0 = (t + 1) * 16;
            ra = *(const float4*)&A[(size_t)(rowB + ar) * 256 + k0 + ac];
            rb = *(const float4*)&B[(size_t)(k0 + br) * 64 + bc];
        }
        #pragma unroll
        for (int kk = 0; kk < 16; kk++) {
            float a[4];
            #pragma unroll
            for (int i = 0; i < 4; i++) a[i] = As[cur][ty * 4 + i][kk];
            float4 bv = *(float4*)&Bs[cur][kk][tx * 4];
            #pragma unroll
            for (int i = 0; i < 4; i++) {
                acc[i][0] += a[i] * bv.x;
                acc[i][1] += a[i] * bv.y;
                acc[i][2] += a[i] * bv.z;
                acc[i][3] += a[i] * bv.w;
            }
        }
        if (t + 1 < 16) {
            int nxt = cur ^ 1;
            *(float4*)&As[nxt][ar][ac] = ra;
            *(float4*)&Bs[nxt][br][bc] = rb;
        }
        __syncthreads();
    }
    // transposed write: C[h][node], float4 over 4 consecutive nodes
    #pragma unroll
    for (int j = 0; j < 4; j++) {
        int col = tx * 4 + j;
        float b = isQ ? 0.f : b1a[col];
        float4 w;
        w.x = acc[0][j] + b; w.y = acc[1][j] + b;
        w.z = acc[2][j] + b; w.w = acc[3][j] + b;
        *(float4*)&C[(size_t)col * NNODES + rowB + ty * 4] = w;
    }
}

// ---------------- per-edge MLPs, feature-major P/Q (coalesced/broadcast) ---------
__global__ void edge_pq(const int* __restrict__ ei, const float* __restrict__ coords,
                        const float* __restrict__ W2a, const float* __restrict__ b2a,
                        const float* __restrict__ W1g, const float* __restrict__ b1g,
                        const float* __restrict__ W2g, const float* __restrict__ b2g,
                        const float* __restrict__ W1f, const float* __restrict__ b1f,
                        const float* __restrict__ W2f, const float* __restrict__ b2f) {
    int e = blockIdx.x * blockDim.x + threadIdx.x;
    if (e >= TWO_E) return;
    int s = ei[e], d = ei[TWO_E + e];

    float a1 = b2a[0];
    #pragma unroll 8
    for (int h = 0; h < 64; h++)
        a1 += fmaxf(g_PT[h * NNODES + s] + g_QT[h * NNODES + d], 0.f) * W2a[h];

    float geo[8];
    float4 cs = *(const float4*)(coords + s * 4);
    float4 cd = *(const float4*)(coords + d * 4);
    geo[0] = cs.x; geo[1] = cs.y; geo[2] = cs.z; geo[3] = cs.w;
    geo[4] = cd.x; geo[5] = cd.y; geo[6] = cd.z; geo[7] = cd.w;
    float a2 = b2g[0];
    #pragma unroll
    for (int h = 0; h < 16; h++) {
        float acc = b1g[h];
        #pragma unroll
        for (int j = 0; j < 8; j++) acc += geo[j] * W1g[j * 16 + h];
        a2 += fmaxf(acc, 0.f) * W2g[h];
    }

    float ev = b2f[0];
    #pragma unroll
    for (int h = 0; h < 8; h++)
        ev += fmaxf(a1 * W1f[h] + a2 * W1f[8 + h] + b1f[h], 0.f) * W2f[h];
    g_emb[e] = ev;
}

// ---------------- msg: block per node, smem-staged edge list ---------------------
__global__ void msg_blk() {                 // grid 2048, block 256
    int n = blockIdx.x, f = threadIdx.x;
    __shared__ float semb[64];
    __shared__ int   ssrc[64];
    if (f < 64) {
        int base = n * 64 + f;
        semb[f] = g_emb[g_csc_eid[base]];
        ssrc[f] = g_csc_src[base] * D_EMBC;
    }
    __syncthreads();
    float acc = 0.f;
    #pragma unroll 8
    for (int k = 0; k < 64; k++) acc += semb[k] * g_node[ssrc[k] + f];
    g_msg[n * D_EMBC + f] = acc;
}

// ---------------- per-node L2 norm, feature-major (coalesced) --------------------
__global__ void norm_t() {                  // grid 64, block 256
    int lane = threadIdx.x & 31;
    int n = blockIdx.x * 32 + lane;
    int fg = threadIdx.x >> 5;              // 0..7
    float s = 0.f;
    #pragma unroll 8
    for (int k = 0; k < 32; k++) {
        float v = g_OT[(size_t)(fg * 32 + k) * NNODES + n];
        s += v * v;
    }
    __shared__ float red[8][32];
    red[fg][lane] = s;
    __syncthreads();
    if (fg == 0) {
        float tot = 0.f;
        #pragma unroll
        for (int i = 0; i < 8; i++) tot += red[i][lane];
        g_norm[n] = sqrtf(tot);
    }
}

// ---------------- affinity, feature-major dot (thread per forward edge) ----------
__global__ void aff_lit(const int* __restrict__ ei, const float* __restrict__ co,
                        const float* __restrict__ W1c, const float* __restrict__ b1c,
                        const float* __restrict__ W2c, const float* __restrict__ b2c) {
    int e = blockIdx.x * blockDim.x + threadIdx.x;
    if (e >= EE) return;
    int t = ei[e], dn = ei[TWO_E + e];
    float dot = 0.f;
    #pragma unroll 8
    for (int f = 0; f < D_EMBC; f++)
        dot += g_OT[(size_t)f * NNODES + t] * g_OT[(size_t)f * NNODES + dn];
    float cosv = dot / fmaxf(g_norm[t] * g_norm[dn], 1e-6f);

    float4 A = *(const float4*)(co + t * 4);
    float4 B = *(const float4*)(co + dn * 4);
    float lt0 = fmaxf(A.x, B.x), lt1 = fmaxf(A.y, B.y);
    float rb0 = fminf(A.z, B.z), rb1 = fminf(A.w, B.w);
    float w = fmaxf(rb0 - lt0, 0.f), h = fmaxf(rb1 - lt1, 0.f);
    float inter = w * h;
    float areaA = (A.z - A.x) * (A.w - A.y);
    float areaB = (B.z - B.x) * (B.w - B.y);
    float iou = inter / (areaA + areaB - inter + 1e-9f);

    float aff = b2c[0];
    #pragma unroll
    for (int hh = 0; hh < 8; hh++)
        aff += fmaxf(cosv * W1c[hh] + iou * W1c[8 + hh] + b1c[hh], 0.f) * W2c[hh];
    float mv = expf(aff * LAMC);
    g_mval[e] = mv;
    g_dstd[e] = dn - T_NUMC;
    g_cval[g_inv[e]] = mv;       // column view (csrc filled in csc_build)
}

// ---------------- persistent sinkhorn v2: 32 blocks x 1024 thr, reg-cached -------
__device__ __forceinline__ void gbarrier(int target) {
    __threadfence();
    __syncthreads();
    if (threadIdx.x == 0) {
        atomicAdd((int*)&g_bar, 1);
        while (g_bar < target) { }
    }
    __syncthreads();
}

__global__ void __launch_bounds__(1024, 1)
sink_fused(float slack, float* __restrict__ out, int out_size) {
    int tid = threadIdx.x, lane = tid & 31;
    int gw = blockIdx.x * 32 + (tid >> 5);     // warp id 0..1023 == row/col id
    int gid = blockIdx.x * 1024 + tid;         // 0..32767

    // register-cache nnz + indices for this warp's row and column
    const float* mv = g_mval + gw * 64;
    const int*   dp = g_dstd + gw * 64;
    const float* cv = g_cval + gw * 64;
    const int*   sp = g_csrc + gw * 64;
    float m0 = mv[lane], m1 = mv[32 + lane];
    int   d0 = dp[lane], d1 = dp[32 + lane];
    float c0 = cv[lane], c1 = cv[32 + lane];
    int   s0 = sp[lane], s1 = sp[32 + lane];

    int barn = 1;
    for (int it = 0; it < 8; it++) {
        // row half-step: u
        float s = m0 * __ldcg(&g_v[d0]) + m1 * __ldcg(&g_v[d1]);
        s = warpsum(s);
        if (lane == 0) {
            s += slack * __ldcg(&g_v[1024]);
            float ur = g_u[gw];
            g_u[gw] = ur / (ur * s + EPSC);
        }
        if (gw == 0) {                         // slack row (warp 0 extra duty)
            float ss = 0.f;
            for (int i = lane; i < 1025; i += 32) ss += __ldcg(&g_v[i]);
            ss = warpsum(ss);
            if (lane == 0) {
                float ur = g_u[1024];
                g_u[1024] = ur / (ur * slack * ss + EPSC);
            }
        }
        gbarrier(barn * SBLK); barn++;

        // col half-step: v
        float sc = c0 * __ldcg(&g_u[s0]) + c1 * __ldcg(&g_u[s1]);
        sc = warpsum(sc);
        if (lane == 0) {
            sc += slack * __ldcg(&g_u[1024]);
            float vc = g_v[gw];
            g_v[gw] = vc / (vc * sc + EPSC);
        }
        if (gw == 0) {
            float ss = 0.f;
            for (int i = lane; i < 1025; i += 32) ss += __ldcg(&g_u[i]);
            ss = warpsum(ss);
            if (lane == 0) {
                float vc = g_v[1024];
                g_v[1024] = vc / (vc * slack * ss + EPSC);
            }
        }
        gbarrier(barn * SBLK); barn++;
    }

    // final scatter: out[t,d] = u[t]*M0*v[d]
    for (int e = gid; e < EE; e += SBLK * 1024) {
        int t = e >> 6;
        int d = g_dstd[e];
        out[(size_t)t * DET_NUMC + d] = __ldcg(&g_u[t]) * g_mval[e] * __ldcg(&g_v[d]);
    }
    if (gid == 0 && out_size >= 2097154) {
        out[2097152] = 1024.0f;  // det_num
        out[2097153] = 1024.0f;  // tracklet_num
    }
}

// =================================================================================
extern "C" void kernel_launch(void* const* d_in, const int* in_sizes, int n_in,
                              void* d_out, int out_size) {
    const float* x      = (const float*)d_in[0];
    const float* coords = (const float*)d_in[1];   // U[0,1) coords -> geo MLP
    const float* co     = (const float*)d_in[2];   // coords_original -> IoU
    const float* gt     = (const float*)d_in[3];
    const int*   ei     = (const int*)  d_in[4];
    const float* W_enc  = (const float*)d_in[5];
    const float* b_enc  = (const float*)d_in[6];
    const float* W1a    = (const float*)d_in[7];
    const float* b1a    = (const float*)d_in[8];
    const float* W2a    = (const float*)d_in[9];
    const float* b2a    = (const float*)d_in[10];
    const float* W1g    = (const float*)d_in[11];
    const float* b1g    = (const float*)d_in[12];
    const float* W2g    = (const float*)d_in[13];
    const float* b2g    = (const float*)d_in[14];
    const float* W1f    = (const float*)d_in[15];
    const float* b1f    = (const float*)d_in[16];
    const float* W2f    = (const float*)d_in[17];
    const float* b2f    = (const float*)d_in[18];
    const float* Wn     = (const float*)d_in[19];
    const float* Wm     = (const float*)d_in[20];
    const float* bo     = (const float*)d_in[21];
    const float* W1c    = (const float*)d_in[22];
    const float* b1c    = (const float*)d_in[23];
    const float* W2c    = (const float*)d_in[24];
    const float* b2c    = (const float*)d_in[25];

    void* p;
    cudaGetSymbolAddress(&p, g_node); float* node = (float*)p;
    cudaGetSymbolAddress(&p, g_msg);  float* msgp = (float*)p;
    cudaGetSymbolAddress(&p, g_OT);   float* otp  = (float*)p;
    void* cntp;  cudaGetSymbolAddress(&cntp, g_cnt);
    void* barp;  cudaGetSymbolAddress(&barp, (const void*)&g_bar);

    cudaMemsetAsync(cntp, 0, NNODES * sizeof(int), 0);
    cudaMemsetAsync(barp, 0, sizeof(int), 0);
    cudaMemsetAsync(d_out, 0, (size_t)T_NUMC * DET_NUMC * sizeof(float), 0);

    csc_build<<<TWO_E / 256, 256>>>(ei);

    // node = relu(x @ W_enc + b_enc)   (row-major out: feeds GEMM A operands)
    sgemm<true, false, false><<<dim3(4, 32), 256>>>(x, W_enc, nullptr, nullptr, b_enc,
                                                    node, NNODES, D_EMBC, 512);
    // PT = (node @ W1a[:256] + b1a)^T ;  QT = (node @ W1a[256:])^T
    pq_gemm<<<dim3(2, 32), 256>>>(node, W1a, b1a);

    edge_pq<<<TWO_E / 256, 256>>>(ei, coords, W2a, b2a,
                                  W1g, b1g, W2g, b2g, W1f, b1f, W2f, b2f);
    msg_blk<<<NNODES, 256>>>();

    // OT = relu(node @ Wn + msg @ Wm + bo)^T   (feature-major for norm/aff)
    sgemm<true, true, true><<<dim3(4, 32), 256>>>(node, Wn, msgp, Wm, bo,
                                                  otp, NNODES, D_EMBC, D_EMBC);

    norm_t<<<64, 256>>>();
    aff_lit<<<EE / 256, 256>>>(ei, co, W1c, b1c, W2c, b2c);

    float slack = expf(-1.0f);  // exp(SLACK*LAM)
    sink_fused<<<SBLK, 1024>>>(slack, (float*)d_out, out_size);

    if (out_size >= 2097152)
        cudaMemcpyAsync((float*)d_out + 1048576, gt, 1048576 * sizeof(float),
                        cudaMemcpyDeviceToDevice, 0);
}

// round 15
// speedup vs baseline: 1.1999x; 1.1999x over previous
#include <cuda_runtime.h>
#include <math.h>

#define T_NUMC   1024
#define DET_NUMC 1024
#define EE       65536       // T_NUM * DEG
#define TWO_E    131072
#define NNODES   2048
#define D_EMBC   256
#define LAMC     5.0f
#define EPSC     1e-9f

// ---------------- scratch (device globals; no allocation allowed) ----------------
__device__ float g_node[NNODES * D_EMBC];          // row-major (GEMM A operand)
__device__ float g_PT[64 * NNODES];                // P transposed: PT[h][n]
__device__ float g_QT[64 * NNODES];                // Q transposed: QT[h][n]
__device__ float g_emb[TWO_E];
__device__ float g_msg[NNODES * D_EMBC];           // row-major (GEMM A operand)
__device__ float g_OT[D_EMBC * NNODES];            // out transposed: OT[f][n]
__device__ float g_norm[NNODES];
__device__ int   g_cnt[NNODES];
__device__ int   g_csc_eid[NNODES * 64];
__device__ int   g_csc_src[NNODES * 64];
__device__ float g_mval[EE];    // M0 nnz, row-major by tracklet (edge e -> row e/64)
__device__ int   g_dstd[EE];    // det column of edge e
__device__ float g_cval[EE];    // M0 nnz, column-major by det
__device__ int   g_csrc[EE];    // tracklet row of column-ordered nnz
__device__ int   g_inv[EE];     // forward edge e -> its column-view slot
__device__ float g_u[1025];
__device__ float g_v[1025];

__device__ __forceinline__ float warpsum(float x) {
    #pragma unroll
    for (int o = 16; o > 0; o >>= 1) x += __shfl_xor_sync(0xffffffffu, x, o);
    return x;
}

// ---------------- CSC build; fills column view + inv index; inits u,v ------------
__global__ void csc_build(const int* __restrict__ ei) {
    int e = blockIdx.x * blockDim.x + threadIdx.x;
    if (e < 1025) { g_u[e] = 1.f; g_v[e] = 1.f; }
    if (e >= TWO_E) return;
    int s = ei[e];
    int d = ei[TWO_E + e];
    int slot = atomicAdd(&g_cnt[d], 1);
    if (slot < 64) {
        g_csc_eid[d * 64 + slot] = e;
        g_csc_src[d * 64 + slot] = s;
        if (d >= T_NUMC) {                      // forward edge: column view entry
            int ci = (d - T_NUMC) * 64 + slot;
            g_csrc[ci] = s;
            g_inv[e] = ci;
        }
    }
}

// ---------------- double-buffered tiled fp32 GEMM --------------------------------
// C = [relu]( A@B (+ A2@B2) (+ bias) ).  BM=BN=64, BK=16, 256 thr, 4x4/thread.
// TRANSC: write C transposed as C[col*M + row] (feature-major).
template <bool RELU, bool DUAL, bool TRANSC>
__global__ void sgemm(const float* __restrict__ A, const float* __restrict__ B,
                      const float* __restrict__ A2, const float* __restrict__ B2,
                      const float* __restrict__ bias, float* __restrict__ C,
                      int M, int N, int K) {
    __shared__ float As[2][64][16];
    __shared__ float Bs[2][16][64];
    __shared__ float As2[DUAL ? 2 : 1][DUAL ? 64 : 1][16];
    __shared__ float Bs2[DUAL ? 2 : 1][DUAL ? 16 : 1][64];

    int tid = threadIdx.x;
    int rowB = blockIdx.y * 64, colB = blockIdx.x * 64;
    int tx = tid & 15, ty = tid >> 4;
    int ar = tid >> 2, ac = (tid & 3) << 2;
    int br = tid >> 4, bc = (tid & 15) << 2;

    float acc[4][4] = {};
    int nT = K / 16;

    float4 ra = *(const float4*)&A[(size_t)(rowB + ar) * K + ac];
    float4 rb = *(const float4*)&B[(size_t)br * N + colB + bc];
    float4 ra2, rb2;
    if (DUAL) {
        ra2 = *(const float4*)&A2[(size_t)(rowB + ar) * K + ac];
        rb2 = *(const float4*)&B2[(size_t)br * N + colB + bc];
    }
    *(float4*)&As[0][ar][ac] = ra;
    *(float4*)&Bs[0][br][bc] = rb;
    if (DUAL) {
        *(float4*)&As2[0][ar][ac] = ra2;
        *(float4*)&Bs2[0][br][bc] = rb2;
    }
    __syncthreads();

    for (int t = 0; t < nT; t++) {
        int cur = t & 1;
        if (t + 1 < nT) {
            int k0 = (t + 1) * 16;
            ra = *(const float4*)&A[(size_t)(rowB + ar) * K + k0 + ac];
            rb = *(const float4*)&B[(size_t)(k0 + br) * N + colB + bc];
            if (DUAL) {
                ra2 = *(const float4*)&A2[(size_t)(rowB + ar) * K + k0 + ac];
                rb2 = *(const float4*)&B2[(size_t)(k0 + br) * N + colB + bc];
            }
        }
        #pragma unroll
        for (int kk = 0; kk < 16; kk++) {
            float a[4];
            #pragma unroll
            for (int i = 0; i < 4; i++) a[i] = As[cur][ty * 4 + i][kk];
            float4 bv = *(float4*)&Bs[cur][kk][tx * 4];
            #pragma unroll
            for (int i = 0; i < 4; i++) {
                acc[i][0] += a[i] * bv.x;
                acc[i][1] += a[i] * bv.y;
                acc[i][2] += a[i] * bv.z;
                acc[i][3] += a[i] * bv.w;
            }
            if (DUAL) {
                float a2[4];
                #pragma unroll
                for (int i = 0; i < 4; i++) a2[i] = As2[cur][ty * 4 + i][kk];
                float4 bv2 = *(float4*)&Bs2[cur][kk][tx * 4];
                #pragma unroll
                for (int i = 0; i < 4; i++) {
                    acc[i][0] += a2[i] * bv2.x;
                    acc[i][1] += a2[i] * bv2.y;
                    acc[i][2] += a2[i] * bv2.z;
                    acc[i][3] += a2[i] * bv2.w;
                }
            }
        }
        if (t + 1 < nT) {
            int nxt = cur ^ 1;
            *(float4*)&As[nxt][ar][ac] = ra;
            *(float4*)&Bs[nxt][br][bc] = rb;
            if (DUAL) {
                *(float4*)&As2[nxt][ar][ac] = ra2;
                *(float4*)&Bs2[nxt][br][bc] = rb2;
            }
        }
        __syncthreads();
    }
    if (TRANSC) {
        #pragma unroll
        for (int j = 0; j < 4; j++) {
            int col = colB + tx * 4 + j;
            float b = bias ? bias[col] : 0.f;
            float4 w;
            w.x = acc[0][j] + b; w.y = acc[1][j] + b;
            w.z = acc[2][j] + b; w.w = acc[3][j] + b;
            if (RELU) {
                w.x = fmaxf(w.x, 0.f); w.y = fmaxf(w.y, 0.f);
                w.z = fmaxf(w.z, 0.f); w.w = fmaxf(w.w, 0.f);
            }
            *(float4*)&C[(size_t)col * M + rowB + ty * 4] = w;
        }
    } else {
        #pragma unroll
        for (int i = 0; i < 4; i++) {
            int row = rowB + ty * 4 + i;
            #pragma unroll
            for (int j = 0; j < 4; j++) {
                int col = colB + tx * 4 + j;
                float v = acc[i][j];
                if (bias) v += bias[col];
                if (RELU) v = fmaxf(v, 0.f);
                C[(size_t)row * N + col] = v;
            }
        }
    }
}

// ---------------- fused, double-buffered P/Q GEMM -> TRANSPOSED outputs ----------
__global__ void pq_gemm(const float* __restrict__ A, const float* __restrict__ W1a,
                        const float* __restrict__ b1a) {
    __shared__ float As[2][64][16];
    __shared__ float Bs[2][16][64];

    int tid = threadIdx.x;
    int rowB = blockIdx.y * 64;
    bool isQ = (blockIdx.x == 1);
    const float* B = W1a + (isQ ? 256 * 64 : 0);
    float* C = isQ ? g_QT : g_PT;

    int tx = tid & 15, ty = tid >> 4;
    int ar = tid >> 2, ac = (tid & 3) << 2;
    int br = tid >> 4, bc = (tid & 15) << 2;

    float acc[4][4] = {};

    float4 ra = *(const float4*)&A[(size_t)(rowB + ar) * 256 + ac];
    float4 rb = *(const float4*)&B[(size_t)br * 64 + bc];
    *(float4*)&As[0][ar][ac] = ra;
    *(float4*)&Bs[0][br][bc] = rb;
    __syncthreads();

    for (int t = 0; t < 16; t++) {
        int cur = t & 1;
        if (t + 1 < 16) {
            int k0 = (t + 1) * 16;
            ra = *(const float4*)&A[(size_t)(rowB + ar) * 256 + k0 + ac];
            rb = *(const float4*)&B[(size_t)(k0 + br) * 64 + bc];
        }
        #pragma unroll
        for (int kk = 0; kk < 16; kk++) {
            float a[4];
            #pragma unroll
            for (int i = 0; i < 4; i++) a[i] = As[cur][ty * 4 + i][kk];
            float4 bv = *(float4*)&Bs[cur][kk][tx * 4];
            #pragma unroll
            for (int i = 0; i < 4; i++) {
                acc[i][0] += a[i] * bv.x;
                acc[i][1] += a[i] * bv.y;
                acc[i][2] += a[i] * bv.z;
                acc[i][3] += a[i] * bv.w;
            }
        }
        if (t + 1 < 16) {
            int nxt = cur ^ 1;
            *(float4*)&As[nxt][ar][ac] = ra;
            *(float4*)&Bs[nxt][br][bc] = rb;
        }
        __syncthreads();
    }
    // transposed write: C[h][node], float4 over 4 consecutive nodes
    #pragma unroll
    for (int j = 0; j < 4; j++) {
        int col = tx * 4 + j;
        float b = isQ ? 0.f : b1a[col];
        float4 w;
        w.x = acc[0][j] + b; w.y = acc[1][j] + b;
        w.z = acc[2][j] + b; w.w = acc[3][j] + b;
        *(float4*)&C[(size_t)col * NNODES + rowB + ty * 4] = w;
    }
}

// ---------------- per-edge MLPs, 2 threads per edge ------------------------------
// half0 (tid<128): a1 partial h=[0,32); half1: a1 partial h=[32,64) + geo MLP.
// Combine via smem; half0 finishes with the 2->8->1 MLP and stores.
__global__ void edge_pq(const int* __restrict__ ei, const float* __restrict__ coords,
                        const float* __restrict__ W2a, const float* __restrict__ b2a,
                        const float* __restrict__ W1g, const float* __restrict__ b1g,
                        const float* __restrict__ W2g, const float* __restrict__ b2g,
                        const float* __restrict__ W1f, const float* __restrict__ b1f,
                        const float* __restrict__ W2f, const float* __restrict__ b2f) {
    __shared__ float s_a1p[128];
    __shared__ float s_a2[128];
    int tid = threadIdx.x;
    int t0 = tid & 127;
    int half = tid >> 7;
    int e = blockIdx.x * 128 + t0;             // grid = TWO_E/128
    int s = ei[e], d = ei[TWO_E + e];

    int hbase = half * 32;
    float a1p = 0.f;
    #pragma unroll 8
    for (int h = 0; h < 32; h++) {
        int hh = hbase + h;
        a1p += fmaxf(g_PT[hh * NNODES + s] + g_QT[hh * NNODES + d], 0.f) * W2a[hh];
    }

    if (half) {
        // geo MLP 8->16->1
        float geo[8];
        float4 cs = *(const float4*)(coords + s * 4);
        float4 cd = *(const float4*)(coords + d * 4);
        geo[0] = cs.x; geo[1] = cs.y; geo[2] = cs.z; geo[3] = cs.w;
        geo[4] = cd.x; geo[5] = cd.y; geo[6] = cd.z; geo[7] = cd.w;
        float a2 = b2g[0];
        #pragma unroll
        for (int h = 0; h < 16; h++) {
            float acc = b1g[h];
            #pragma unroll
            for (int j = 0; j < 8; j++) acc += geo[j] * W1g[j * 16 + h];
            a2 += fmaxf(acc, 0.f) * W2g[h];
        }
        s_a1p[t0] = a1p;
        s_a2[t0]  = a2;
    }
    __syncthreads();
    if (!half) {
        float a1 = a1p + s_a1p[t0] + b2a[0];
        float a2 = s_a2[t0];
        float ev = b2f[0];
        #pragma unroll
        for (int h = 0; h < 8; h++)
            ev += fmaxf(a1 * W1f[h] + a2 * W1f[8 + h] + b1f[h], 0.f) * W2f[h];
        g_emb[e] = ev;
    }
}

// ---------------- msg: block per node, smem-staged edge list ---------------------
__global__ void msg_blk() {                 // grid 2048, block 256
    int n = blockIdx.x, f = threadIdx.x;
    __shared__ float semb[64];
    __shared__ int   ssrc[64];
    if (f < 64) {
        int base = n * 64 + f;
        semb[f] = g_emb[g_csc_eid[base]];
        ssrc[f] = g_csc_src[base] * D_EMBC;
    }
    __syncthreads();
    float acc = 0.f;
    #pragma unroll 8
    for (int k = 0; k < 64; k++) acc += semb[k] * g_node[ssrc[k] + f];
    g_msg[n * D_EMBC + f] = acc;
}

// ---------------- per-node L2 norm, feature-major (coalesced) --------------------
__global__ void norm_t() {                  // grid 64, block 256
    int lane = threadIdx.x & 31;
    int n = blockIdx.x * 32 + lane;
    int fg = threadIdx.x >> 5;              // 0..7
    float s = 0.f;
    #pragma unroll 8
    for (int k = 0; k < 32; k++) {
        float v = g_OT[(size_t)(fg * 32 + k) * NNODES + n];
        s += v * v;
    }
    __shared__ float red[8][32];
    red[fg][lane] = s;
    __syncthreads();
    if (fg == 0) {
        float tot = 0.f;
        #pragma unroll
        for (int i = 0; i < 8; i++) tot += red[i][lane];
        g_norm[n] = sqrtf(tot);
    }
}

// ---------------- affinity: 4 threads per forward edge (quad-split dot) ----------
__global__ void aff_quad(const int* __restrict__ ei, const float* __restrict__ co,
                         const float* __restrict__ W1c, const float* __restrict__ b1c,
                         const float* __restrict__ W2c, const float* __restrict__ b2c) {
    int gid = blockIdx.x * blockDim.x + threadIdx.x;   // grid = EE*4/256
    int e = gid >> 2, q = gid & 3;
    int t = ei[e], dn = ei[TWO_E + e];

    float dot = 0.f;
    int fbase = q * 64;
    #pragma unroll 8
    for (int k = 0; k < 64; k++) {
        int f = fbase + k;
        dot += g_OT[(size_t)f * NNODES + t] * g_OT[(size_t)f * NNODES + dn];
    }
    // reduce within aligned quad
    dot += __shfl_xor_sync(0xffffffffu, dot, 1);
    dot += __shfl_xor_sync(0xffffffffu, dot, 2);

    if (q == 0) {
        float cosv = dot / fmaxf(g_norm[t] * g_norm[dn], 1e-6f);
        float4 A = *(const float4*)(co + t * 4);
        float4 B = *(const float4*)(co + dn * 4);
        float lt0 = fmaxf(A.x, B.x), lt1 = fmaxf(A.y, B.y);
        float rb0 = fminf(A.z, B.z), rb1 = fminf(A.w, B.w);
        float w = fmaxf(rb0 - lt0, 0.f), h = fmaxf(rb1 - lt1, 0.f);
        float inter = w * h;
        float areaA = (A.z - A.x) * (A.w - A.y);
        float areaB = (B.z - B.x) * (B.w - B.y);
        float iou = inter / (areaA + areaB - inter + 1e-9f);

        float aff = b2c[0];
        #pragma unroll
        for (int hh = 0; hh < 8; hh++)
            aff += fmaxf(cosv * W1c[hh] + iou * W1c[8 + hh] + b1c[hh], 0.f) * W2c[hh];
        float mv = expf(aff * LAMC);
        g_mval[e] = mv;
        g_dstd[e] = dn - T_NUMC;
        g_cval[g_inv[e]] = mv;       // column view (csrc filled in csc_build)
    }
}

// ---------------- factorized sinkhorn half-steps (warp per row, coalesced) -------
__global__ void sink_row(float slack) {
    int tid = threadIdx.x, lane = tid & 31, wid = tid >> 5;
    if (blockIdx.x < 128) {
        int r = blockIdx.x * 8 + wid;
        const float* mv = g_mval + r * 64;
        const int*   dp = g_dstd + r * 64;
        float s = mv[lane] * g_v[dp[lane]] + mv[32 + lane] * g_v[dp[32 + lane]];
        s = warpsum(s);
        if (lane == 0) {
            s += slack * g_v[1024];
            float ur = g_u[r];
            g_u[r] = ur / (ur * s + EPSC);
        }
    } else {
        float s = 0.f;
        for (int i = tid; i < 1025; i += 256) s += g_v[i];
        __shared__ float red[8];
        float w = warpsum(s);
        if (lane == 0) red[wid] = w;
        __syncthreads();
        if (tid == 0) {
            float tot = 0.f;
            #pragma unroll
            for (int i = 0; i < 8; i++) tot += red[i];
            float ur = g_u[1024];
            g_u[1024] = ur / (ur * slack * tot + EPSC);
        }
    }
}

__global__ void sink_col(float slack) {
    int tid = threadIdx.x, lane = tid & 31, wid = tid >> 5;
    if (blockIdx.x < 128) {
        int c = blockIdx.x * 8 + wid;
        const float* cv = g_cval + c * 64;
        const int*   sp = g_csrc + c * 64;
        float s = cv[lane] * g_u[sp[lane]] + cv[32 + lane] * g_u[sp[32 + lane]];
        s = warpsum(s);
        if (lane == 0) {
            s += slack * g_u[1024];
            float vc = g_v[c];
            g_v[c] = vc / (vc * s + EPSC);
        }
    } else {
        float s = 0.f;
        for (int i = tid; i < 1025; i += 256) s += g_u[i];
        __shared__ float red[8];
        float w = warpsum(s);
        if (lane == 0) red[wid] = w;
        __syncthreads();
        if (tid == 0) {
            float tot = 0.f;
            #pragma unroll
            for (int i = 0; i < 8; i++) tot += red[i];
            float vc = g_v[1024];
            g_v[1024] = vc / (vc * slack * tot + EPSC);
        }
    }
}

// ---------------- final scatter: out[t,d] = u[t]*M0*v[d]; scalars ----------------
__global__ void out_scatter(float* __restrict__ out, int out_size) {
    int e = blockIdx.x * blockDim.x + threadIdx.x;
    if (e < EE) {
        int t = e >> 6;
        int d = g_dstd[e];
        out[(size_t)t * DET_NUMC + d] = g_u[t] * g_mval[e] * g_v[d];
    }
    if (e == 0 && out_size >= 2097154) {
        out[2097152] = 1024.0f;  // det_num
        out[2097153] = 1024.0f;  // tracklet_num
    }
}

// =================================================================================
extern "C" void kernel_launch(void* const* d_in, const int* in_sizes, int n_in,
                              void* d_out, int out_size) {
    const float* x      = (const float*)d_in[0];
    const float* coords = (const float*)d_in[1];   // U[0,1) coords -> geo MLP
    const float* co     = (const float*)d_in[2];   // coords_original -> IoU
    const float* gt     = (const float*)d_in[3];
    const int*   ei     = (const int*)  d_in[4];
    const float* W_enc  = (const float*)d_in[5];
    const float* b_enc  = (const float*)d_in[6];
    const float* W1a    = (const float*)d_in[7];
    const float* b1a    = (const float*)d_in[8];
    const float* W2a    = (const float*)d_in[9];
    const float* b2a    = (const float*)d_in[10];
    const float* W1g    = (const float*)d_in[11];
    const float* b1g    = (const float*)d_in[12];
    const float* W2g    = (const float*)d_in[13];
    const float* b2g    = (const float*)d_in[14];
    const float* W1f    = (const float*)d_in[15];
    const float* b1f    = (const float*)d_in[16];
    const float* W2f    = (const float*)d_in[17];
    const float* b2f    = (const float*)d_in[18];
    const float* Wn     = (const float*)d_in[19];
    const float* Wm     = (const float*)d_in[20];
    const float* bo     = (const float*)d_in[21];
    const float* W1c    = (const float*)d_in[22];
    const float* b1c    = (const float*)d_in[23];
    const float* W2c    = (const float*)d_in[24];
    const float* b2c    = (const float*)d_in[25];

    void* p;
    cudaGetSymbolAddress(&p, g_node); float* node = (float*)p;
    cudaGetSymbolAddress(&p, g_msg);  float* msgp = (float*)p;
    cudaGetSymbolAddress(&p, g_OT);   float* otp  = (float*)p;
    void* cntp;  cudaGetSymbolAddress(&cntp, g_cnt);

    cudaMemsetAsync(cntp, 0, NNODES * sizeof(int), 0);
    cudaMemsetAsync(d_out, 0, (size_t)T_NUMC * DET_NUMC * sizeof(float), 0);

    csc_build<<<TWO_E / 256, 256>>>(ei);

    // node = relu(x @ W_enc + b_enc)   (row-major out: feeds GEMM A operands)
    sgemm<true, false, false><<<dim3(4, 32), 256>>>(x, W_enc, nullptr, nullptr, b_enc,
                                                    node, NNODES, D_EMBC, 512);
    // PT = (node @ W1a[:256] + b1a)^T ;  QT = (node @ W1a[256:])^T
    pq_gemm<<<dim3(2, 32), 256>>>(node, W1a, b1a);

    edge_pq<<<TWO_E / 128, 256>>>(ei, coords, W2a, b2a,
                                  W1g, b1g, W2g, b2g, W1f, b1f, W2f, b2f);
    msg_blk<<<NNODES, 256>>>();

    // OT = relu(node @ Wn + msg @ Wm + bo)^T   (feature-major for norm/aff)
    sgemm<true, true, true><<<dim3(4, 32), 256>>>(node, Wn, msgp, Wm, bo,
                                                  otp, NNODES, D_EMBC, D_EMBC);

    norm_t<<<64, 256>>>();
    aff_quad<<<EE * 4 / 256, 256>>>(ei, co, W1c, b1c, W2c, b2c);

    float slack = expf(-1.0f);  // exp(SLACK*LAM)
    for (int it = 0; it < 8; it++) {
        sink_row<<<129, 256>>>(slack);
        sink_col<<<129, 256>>>(slack);
    }

    out_scatter<<<EE / 256, 256>>>((float*)d_out, out_size);
    if (out_size >= 2097152)
        cudaMemcpyAsync((float*)d_out + 1048576, gt, 1048576 * sizeof(float),
                        cudaMemcpyDeviceToDevice, 0);
}

// round 16
// speedup vs baseline: 1.2862x; 1.0719x over previous
#include <cuda_runtime.h>
#include <math.h>

#define T_NUMC   1024
#define DET_NUMC 1024
#define EE       65536       // T_NUM * DEG
#define TWO_E    131072
#define NNODES   2048
#define D_EMBC   256
#define LAMC     5.0f
#define EPSC     1e-9f

// ---------------- scratch (device globals; no allocation allowed) ----------------
__device__ float g_node[NNODES * D_EMBC];          // row-major (GEMM A operand)
__device__ float g_PT[64 * NNODES];                // P transposed: PT[h][n]
__device__ float g_QT[64 * NNODES];                // Q transposed: QT[h][n]
__device__ float g_emb[TWO_E];
__device__ float g_msg[NNODES * D_EMBC];           // row-major (GEMM A operand)
__device__ float g_OT[D_EMBC * NNODES];            // out transposed: OT[f][n]
__device__ float g_norm[NNODES];
__device__ int   g_cnt[NNODES];
__device__ int   g_csc_eid[NNODES * 64];
__device__ int   g_csc_src[NNODES * 64];
__device__ float g_mval[EE];    // M0 nnz, row-major by tracklet (edge e -> row e/64)
__device__ int   g_dstd[EE];    // det column of edge e
__device__ float g_cval[EE];    // M0 nnz, column-major by det
__device__ int   g_csrc[EE];    // tracklet row of column-ordered nnz
__device__ int   g_inv[EE];     // forward edge e -> its column-view slot
__device__ float g_u[1025];
__device__ float g_v[1025];

__device__ __forceinline__ float warpsum(float x) {
    #pragma unroll
    for (int o = 16; o > 0; o >>= 1) x += __shfl_xor_sync(0xffffffffu, x, o);
    return x;
}

// ---------------- CSC build; fills column view + inv index; inits u,v ------------
__global__ void csc_build(const int* __restrict__ ei) {
    int e = blockIdx.x * blockDim.x + threadIdx.x;
    if (e < 1025) { g_u[e] = 1.f; g_v[e] = 1.f; }
    if (e >= TWO_E) return;
    int s = ei[e];
    int d = ei[TWO_E + e];
    int slot = atomicAdd(&g_cnt[d], 1);
    if (slot < 64) {
        g_csc_eid[d * 64 + slot] = e;
        g_csc_src[d * 64 + slot] = s;
        if (d >= T_NUMC) {                      // forward edge: column view entry
            int ci = (d - T_NUMC) * 64 + slot;
            g_csrc[ci] = s;
            g_inv[e] = ci;
        }
    }
}

// ---------------- double-buffered tiled fp32 GEMM --------------------------------
// C = [relu]( A@B (+ A2@B2) (+ bias) ).  BM=BN=64, BK=16, 256 thr, 4x4/thread.
// TRANSC: write C transposed as C[col*M + row] (feature-major).
template <bool RELU, bool DUAL, bool TRANSC>
__global__ void sgemm(const float* __restrict__ A, const float* __restrict__ B,
                      const float* __restrict__ A2, const float* __restrict__ B2,
                      const float* __restrict__ bias, float* __restrict__ C,
                      int M, int N, int K) {
    __shared__ float As[2][64][16];
    __shared__ float Bs[2][16][64];
    __shared__ float As2[DUAL ? 2 : 1][DUAL ? 64 : 1][16];
    __shared__ float Bs2[DUAL ? 2 : 1][DUAL ? 16 : 1][64];

    int tid = threadIdx.x;
    int rowB = blockIdx.y * 64, colB = blockIdx.x * 64;
    int tx = tid & 15, ty = tid >> 4;
    int ar = tid >> 2, ac = (tid & 3) << 2;
    int br = tid >> 4, bc = (tid & 15) << 2;

    float acc[4][4] = {};
    int nT = K / 16;

    float4 ra = *(const float4*)&A[(size_t)(rowB + ar) * K + ac];
    float4 rb = *(const float4*)&B[(size_t)br * N + colB + bc];
    float4 ra2, rb2;
    if (DUAL) {
        ra2 = *(const float4*)&A2[(size_t)(rowB + ar) * K + ac];
        rb2 = *(const float4*)&B2[(size_t)br * N + colB + bc];
    }
    *(float4*)&As[0][ar][ac] = ra;
    *(float4*)&Bs[0][br][bc] = rb;
    if (DUAL) {
        *(float4*)&As2[0][ar][ac] = ra2;
        *(float4*)&Bs2[0][br][bc] = rb2;
    }
    __syncthreads();

    for (int t = 0; t < nT; t++) {
        int cur = t & 1;
        if (t + 1 < nT) {
            int k0 = (t + 1) * 16;
            ra = *(const float4*)&A[(size_t)(rowB + ar) * K + k0 + ac];
            rb = *(const float4*)&B[(size_t)(k0 + br) * N + colB + bc];
            if (DUAL) {
                ra2 = *(const float4*)&A2[(size_t)(rowB + ar) * K + k0 + ac];
                rb2 = *(const float4*)&B2[(size_t)(k0 + br) * N + colB + bc];
            }
        }
        #pragma unroll
        for (int kk = 0; kk < 16; kk++) {
            float a[4];
            #pragma unroll
            for (int i = 0; i < 4; i++) a[i] = As[cur][ty * 4 + i][kk];
            float4 bv = *(float4*)&Bs[cur][kk][tx * 4];
            #pragma unroll
            for (int i = 0; i < 4; i++) {
                acc[i][0] += a[i] * bv.x;
                acc[i][1] += a[i] * bv.y;
                acc[i][2] += a[i] * bv.z;
                acc[i][3] += a[i] * bv.w;
            }
            if (DUAL) {
                float a2[4];
                #pragma unroll
                for (int i = 0; i < 4; i++) a2[i] = As2[cur][ty * 4 + i][kk];
                float4 bv2 = *(float4*)&Bs2[cur][kk][tx * 4];
                #pragma unroll
                for (int i = 0; i < 4; i++) {
                    acc[i][0] += a2[i] * bv2.x;
                    acc[i][1] += a2[i] * bv2.y;
                    acc[i][2] += a2[i] * bv2.z;
                    acc[i][3] += a2[i] * bv2.w;
                }
            }
        }
        if (t + 1 < nT) {
            int nxt = cur ^ 1;
            *(float4*)&As[nxt][ar][ac] = ra;
            *(float4*)&Bs[nxt][br][bc] = rb;
            if (DUAL) {
                *(float4*)&As2[nxt][ar][ac] = ra2;
                *(float4*)&Bs2[nxt][br][bc] = rb2;
            }
        }
        __syncthreads();
    }
    if (TRANSC) {
        #pragma unroll
        for (int j = 0; j < 4; j++) {
            int col = colB + tx * 4 + j;
            float b = bias ? bias[col] : 0.f;
            float4 w;
            w.x = acc[0][j] + b; w.y = acc[1][j] + b;
            w.z = acc[2][j] + b; w.w = acc[3][j] + b;
            if (RELU) {
                w.x = fmaxf(w.x, 0.f); w.y = fmaxf(w.y, 0.f);
                w.z = fmaxf(w.z, 0.f); w.w = fmaxf(w.w, 0.f);
            }
            *(float4*)&C[(size_t)col * M + rowB + ty * 4] = w;
        }
    } else {
        #pragma unroll
        for (int i = 0; i < 4; i++) {
            int row = rowB + ty * 4 + i;
            #pragma unroll
            for (int j = 0; j < 4; j++) {
                int col = colB + tx * 4 + j;
                float v = acc[i][j];
                if (bias) v += bias[col];
                if (RELU) v = fmaxf(v, 0.f);
                C[(size_t)row * N + col] = v;
            }
        }
    }
}

// ---------------- fused, double-buffered P/Q GEMM -> TRANSPOSED outputs ----------
__global__ void pq_gemm(const float* __restrict__ A, const float* __restrict__ W1a,
                        const float* __restrict__ b1a) {
    __shared__ float As[2][64][16];
    __shared__ float Bs[2][16][64];

    int tid = threadIdx.x;
    int rowB = blockIdx.y * 64;
    bool isQ = (blockIdx.x == 1);
    const float* B = W1a + (isQ ? 256 * 64 : 0);
    float* C = isQ ? g_QT : g_PT;

    int tx = tid & 15, ty = tid >> 4;
    int ar = tid >> 2, ac = (tid & 3) << 2;
    int br = tid >> 4, bc = (tid & 15) << 2;

    float acc[4][4] = {};

    float4 ra = *(const float4*)&A[(size_t)(rowB + ar) * 256 + ac];
    float4 rb = *(const float4*)&B[(size_t)br * 64 + bc];
    *(float4*)&As[0][ar][ac] = ra;
    *(float4*)&Bs[0][br][bc] = rb;
    __syncthreads();

    for (int t = 0; t < 16; t++) {
        int cur = t & 1;
        if (t + 1 < 16) {
            int k0 = (t + 1) * 16;
            ra = *(const float4*)&A[(size_t)(rowB + ar) * 256 + k0 + ac];
            rb = *(const float4*)&B[(size_t)(k0 + br) * 64 + bc];
        }
        #pragma unroll
        for (int kk = 0; kk < 16; kk++) {
            float a[4];
            #pragma unroll
            for (int i = 0; i < 4; i++) a[i] = As[cur][ty * 4 + i][kk];
            float4 bv = *(float4*)&Bs[cur][kk][tx * 4];
            #pragma unroll
            for (int i = 0; i < 4; i++) {
                acc[i][0] += a[i] * bv.x;
                acc[i][1] += a[i] * bv.y;
                acc[i][2] += a[i] * bv.z;
                acc[i][3] += a[i] * bv.w;
            }
        }
        if (t + 1 < 16) {
            int nxt = cur ^ 1;
            *(float4*)&As[nxt][ar][ac] = ra;
            *(float4*)&Bs[nxt][br][bc] = rb;
        }
        __syncthreads();
    }
    // transposed write: C[h][node], float4 over 4 consecutive nodes
    #pragma unroll
    for (int j = 0; j < 4; j++) {
        int col = tx * 4 + j;
        float b = isQ ? 0.f : b1a[col];
        float4 w;
        w.x = acc[0][j] + b; w.y = acc[1][j] + b;
        w.z = acc[2][j] + b; w.w = acc[3][j] + b;
        *(float4*)&C[(size_t)col * NNODES + rowB + ty * 4] = w;
    }
}

// ---------------- per-edge MLPs, 2 threads per edge (block-half split) -----------
__global__ void edge_pq(const int* __restrict__ ei, const float* __restrict__ coords,
                        const float* __restrict__ W2a, const float* __restrict__ b2a,
                        const float* __restrict__ W1g, const float* __restrict__ b1g,
                        const float* __restrict__ W2g, const float* __restrict__ b2g,
                        const float* __restrict__ W1f, const float* __restrict__ b1f,
                        const float* __restrict__ W2f, const float* __restrict__ b2f) {
    __shared__ float s_a1p[128];
    __shared__ float s_a2[128];
    int tid = threadIdx.x;
    int t0 = tid & 127;
    int half = tid >> 7;
    int e = blockIdx.x * 128 + t0;             // grid = TWO_E/128
    int s = ei[e], d = ei[TWO_E + e];

    int hbase = half * 32;
    float a1p = 0.f;
    #pragma unroll 8
    for (int h = 0; h < 32; h++) {
        int hh = hbase + h;
        a1p += fmaxf(g_PT[hh * NNODES + s] + g_QT[hh * NNODES + d], 0.f) * W2a[hh];
    }

    if (half) {
        // geo MLP 8->16->1
        float geo[8];
        float4 cs = *(const float4*)(coords + s * 4);
        float4 cd = *(const float4*)(coords + d * 4);
        geo[0] = cs.x; geo[1] = cs.y; geo[2] = cs.z; geo[3] = cs.w;
        geo[4] = cd.x; geo[5] = cd.y; geo[6] = cd.z; geo[7] = cd.w;
        float a2 = b2g[0];
        #pragma unroll
        for (int h = 0; h < 16; h++) {
            float acc = b1g[h];
            #pragma unroll
            for (int j = 0; j < 8; j++) acc += geo[j] * W1g[j * 16 + h];
            a2 += fmaxf(acc, 0.f) * W2g[h];
        }
        s_a1p[t0] = a1p;
        s_a2[t0]  = a2;
    }
    __syncthreads();
    if (!half) {
        float a1 = a1p + s_a1p[t0] + b2a[0];
        float a2 = s_a2[t0];
        float ev = b2f[0];
        #pragma unroll
        for (int h = 0; h < 8; h++)
            ev += fmaxf(a1 * W1f[h] + a2 * W1f[8 + h] + b1f[h], 0.f) * W2f[h];
        g_emb[e] = ev;
    }
}

// ---------------- msg: block per node, smem-staged edge list ---------------------
__global__ void msg_blk() {                 // grid 2048, block 256
    int n = blockIdx.x, f = threadIdx.x;
    __shared__ float semb[64];
    __shared__ int   ssrc[64];
    if (f < 64) {
        int base = n * 64 + f;
        semb[f] = g_emb[g_csc_eid[base]];
        ssrc[f] = g_csc_src[base] * D_EMBC;
    }
    __syncthreads();
    float acc = 0.f;
    #pragma unroll 8
    for (int k = 0; k < 64; k++) acc += semb[k] * g_node[ssrc[k] + f];
    g_msg[n * D_EMBC + f] = acc;
}

// ---------------- per-node L2 norm, feature-major (coalesced) --------------------
__global__ void norm_t() {                  // grid 64, block 256
    int lane = threadIdx.x & 31;
    int n = blockIdx.x * 32 + lane;
    int fg = threadIdx.x >> 5;              // 0..7
    float s = 0.f;
    #pragma unroll 8
    for (int k = 0; k < 32; k++) {
        float v = g_OT[(size_t)(fg * 32 + k) * NNODES + n];
        s += v * v;
    }
    __shared__ float red[8][32];
    red[fg][lane] = s;
    __syncthreads();
    if (fg == 0) {
        float tot = 0.f;
        #pragma unroll
        for (int i = 0; i < 8; i++) tot += red[i][lane];
        g_norm[n] = sqrtf(tot);
    }
}

// ---------------- affinity: 2 threads per edge (block-half split, coalesced) -----
// half0: dot over f=[0,128); half1: dot over f=[128,256). Warps stay on 32
// consecutive edges at one f -> one 128B line per load (round-13 pattern kept).
__global__ void aff_half(const int* __restrict__ ei, const float* __restrict__ co,
                         const float* __restrict__ W1c, const float* __restrict__ b1c,
                         const float* __restrict__ W2c, const float* __restrict__ b2c) {
    __shared__ float s_dot[128];
    int tid = threadIdx.x;
    int t0 = tid & 127;
    int half = tid >> 7;
    int e = blockIdx.x * 128 + t0;             // grid = EE/128
    int t = ei[e], dn = ei[TWO_E + e];

    float dot = 0.f;
    int fbase = half * 128;
    #pragma unroll 8
    for (int k = 0; k < 128; k++) {
        int f = fbase + k;
        dot += g_OT[(size_t)f * NNODES + t] * g_OT[(size_t)f * NNODES + dn];
    }
    if (half) {
        s_dot[t0] = dot;
    }
    __syncthreads();
    if (!half) {
        dot += s_dot[t0];
        float cosv = dot / fmaxf(g_norm[t] * g_norm[dn], 1e-6f);

        float4 A = *(const float4*)(co + t * 4);
        float4 B = *(const float4*)(co + dn * 4);
        float lt0 = fmaxf(A.x, B.x), lt1 = fmaxf(A.y, B.y);
        float rb0 = fminf(A.z, B.z), rb1 = fminf(A.w, B.w);
        float w = fmaxf(rb0 - lt0, 0.f), h = fmaxf(rb1 - lt1, 0.f);
        float inter = w * h;
        float areaA = (A.z - A.x) * (A.w - A.y);
        float areaB = (B.z - B.x) * (B.w - B.y);
        float iou = inter / (areaA + areaB - inter + 1e-9f);

        float aff = b2c[0];
        #pragma unroll
        for (int hh = 0; hh < 8; hh++)
            aff += fmaxf(cosv * W1c[hh] + iou * W1c[8 + hh] + b1c[hh], 0.f) * W2c[hh];
        float mv = expf(aff * LAMC);
        g_mval[e] = mv;
        g_dstd[e] = dn - T_NUMC;
        g_cval[g_inv[e]] = mv;       // column view (csrc filled in csc_build)
    }
}

// ---------------- factorized sinkhorn half-steps (warp per row, coalesced) -------
__global__ void sink_row(float slack) {
    int tid = threadIdx.x, lane = tid & 31, wid = tid >> 5;
    if (blockIdx.x < 128) {
        int r = blockIdx.x * 8 + wid;
        const float* mv = g_mval + r * 64;
        const int*   dp = g_dstd + r * 64;
        float s = mv[lane] * g_v[dp[lane]] + mv[32 + lane] * g_v[dp[32 + lane]];
        s = warpsum(s);
        if (lane == 0) {
            s += slack * g_v[1024];
            float ur = g_u[r];
            g_u[r] = ur / (ur * s + EPSC);
        }
    } else {
        float s = 0.f;
        for (int i = tid; i < 1025; i += 256) s += g_v[i];
        __shared__ float red[8];
        float w = warpsum(s);
        if (lane == 0) red[wid] = w;
        __syncthreads();
        if (tid == 0) {
            float tot = 0.f;
            #pragma unroll
            for (int i = 0; i < 8; i++) tot += red[i];
            float ur = g_u[1024];
            g_u[1024] = ur / (ur * slack * tot + EPSC);
        }
    }
}

__global__ void sink_col(float slack) {
    int tid = threadIdx.x, lane = tid & 31, wid = tid >> 5;
    if (blockIdx.x < 128) {
        int c = blockIdx.x * 8 + wid;
        const float* cv = g_cval + c * 64;
        const int*   sp = g_csrc + c * 64;
        float s = cv[lane] * g_u[sp[lane]] + cv[32 + lane] * g_u[sp[32 + lane]];
        s = warpsum(s);
        if (lane == 0) {
            s += slack * g_u[1024];
            float vc = g_v[c];
            g_v[c] = vc / (vc * s + EPSC);
        }
    } else {
        float s = 0.f;
        for (int i = tid; i < 1025; i += 256) s += g_u[i];
        __shared__ float red[8];
        float w = warpsum(s);
        if (lane == 0) red[wid] = w;
        __syncthreads();
        if (tid == 0) {
            float tot = 0.f;
            #pragma unroll
            for (int i = 0; i < 8; i++) tot += red[i];
            float vc = g_v[1024];
            g_v[1024] = vc / (vc * slack * tot + EPSC);
        }
    }
}

// ---------------- final scatter: out[t,d] = u[t]*M0*v[d]; scalars ----------------
__global__ void out_scatter(float* __restrict__ out, int out_size) {
    int e = blockIdx.x * blockDim.x + threadIdx.x;
    if (e < EE) {
        int t = e >> 6;
        int d = g_dstd[e];
        out[(size_t)t * DET_NUMC + d] = g_u[t] * g_mval[e] * g_v[d];
    }
    if (e == 0 && out_size >= 2097154) {
        out[2097152] = 1024.0f;  // det_num
        out[2097153] = 1024.0f;  // tracklet_num
    }
}

// =================================================================================
extern "C" void kernel_launch(void* const* d_in, const int* in_sizes, int n_in,
                              void* d_out, int out_size) {
    const float* x      = (const float*)d_in[0];
    const float* coords = (const float*)d_in[1];   // U[0,1) coords -> geo MLP
    const float* co     = (const float*)d_in[2];   // coords_original -> IoU
    const float* gt     = (const float*)d_in[3];
    const int*   ei     = (const int*)  d_in[4];
    const float* W_enc  = (const float*)d_in[5];
    const float* b_enc  = (const float*)d_in[6];
    const float* W1a    = (const float*)d_in[7];
    const float* b1a    = (const float*)d_in[8];
    const float* W2a    = (const float*)d_in[9];
    const float* b2a    = (const float*)d_in[10];
    const float* W1g    = (const float*)d_in[11];
    const float* b1g    = (const float*)d_in[12];
    const float* W2g    = (const float*)d_in[13];
    const float* b2g    = (const float*)d_in[14];
    const float* W1f    = (const float*)d_in[15];
    const float* b1f    = (const float*)d_in[16];
    const float* W2f    = (const float*)d_in[17];
    const float* b2f    = (const float*)d_in[18];
    const float* Wn     = (const float*)d_in[19];
    const float* Wm     = (const float*)d_in[20];
    const float* bo     = (const float*)d_in[21];
    const float* W1c    = (const float*)d_in[22];
    const float* b1c    = (const float*)d_in[23];
    const float* W2c    = (const float*)d_in[24];
    const float* b2c    = (const float*)d_in[25];

    void* p;
    cudaGetSymbolAddress(&p, g_node); float* node = (float*)p;
    cudaGetSymbolAddress(&p, g_msg);  float* msgp = (float*)p;
    cudaGetSymbolAddress(&p, g_OT);   float* otp  = (float*)p;
    void* cntp;  cudaGetSymbolAddress(&cntp, g_cnt);

    cudaMemsetAsync(cntp, 0, NNODES * sizeof(int), 0);
    cudaMemsetAsync(d_out, 0, (size_t)T_NUMC * DET_NUMC * sizeof(float), 0);

    csc_build<<<TWO_E / 256, 256>>>(ei);

    // node = relu(x @ W_enc + b_enc)   (row-major out: feeds GEMM A operands)
    sgemm<true, false, false><<<dim3(4, 32), 256>>>(x, W_enc, nullptr, nullptr, b_enc,
                                                    node, NNODES, D_EMBC, 512);
    // PT = (node @ W1a[:256] + b1a)^T ;  QT = (node @ W1a[256:])^T
    pq_gemm<<<dim3(2, 32), 256>>>(node, W1a, b1a);

    edge_pq<<<TWO_E / 128, 256>>>(ei, coords, W2a, b2a,
                                  W1g, b1g, W2g, b2g, W1f, b1f, W2f, b2f);
    msg_blk<<<NNODES, 256>>>();

    // OT = relu(node @ Wn + msg @ Wm + bo)^T   (feature-major for norm/aff)
    sgemm<true, true, true><<<dim3(4, 32), 256>>>(node, Wn, msgp, Wm, bo,
                                                  otp, NNODES, D_EMBC, D_EMBC);

    norm_t<<<64, 256>>>();
    aff_half<<<EE / 128, 256>>>(ei, co, W1c, b1c, W2c, b2c);

    float slack = expf(-1.0f);  // exp(SLACK*LAM)
    for (int it = 0; it < 8; it++) {
        sink_row<<<129, 256>>>(slack);
        sink_col<<<129, 256>>>(slack);
    }

    out_scatter<<<EE / 256, 256>>>((float*)d_out, out_size);
    if (out_size >= 2097152)
        cudaMemcpyAsync((float*)d_out + 1048576, gt, 1048576 * sizeof(float),
                        cudaMemcpyDeviceToDevice, 0);
}